// round 5
// baseline (speedup 1.0000x reference)
#include <cuda_runtime.h>
#include <stdint.h>

// Dims (fixed):
//   x:               [64, 64, 4096]   float32
//   cache:           [128, 512, 4096] float32
//   running_seqs:    [64] int32 (arange)
//   idx_salient_row: [64, 64] int32
//   out:             [64, 512, 4096]  float32
//
// out[i, r, :] = x[i, j_last, :] where j_last = last j with idx[i,j]==r
//                (== max matching j), else cache[running_seqs[i], r, :].

#define N_RUNNING    64
#define K_SALIENT    64
#define ROWS_PER_SEQ 512
#define HIDDEN       4096
#define THREADS      128
// Per row: 4096 floats = 512 float8 (32B) vectors; 128 threads -> 4 each.

// 256-bit global load/store (sm_100a: LDG.E.256 / STG.E.256), streaming hint.
__device__ __forceinline__ void ldg256_cs(const float* p, float* v) {
    asm volatile("ld.global.cs.v8.f32 {%0,%1,%2,%3,%4,%5,%6,%7}, [%8];"
                 : "=f"(v[0]), "=f"(v[1]), "=f"(v[2]), "=f"(v[3]),
                   "=f"(v[4]), "=f"(v[5]), "=f"(v[6]), "=f"(v[7])
                 : "l"(p));
}
__device__ __forceinline__ void stg256_cs(float* p, const float* v) {
    asm volatile("st.global.cs.v8.f32 [%0], {%1,%2,%3,%4,%5,%6,%7,%8};"
                 :: "l"(p),
                    "f"(v[0]), "f"(v[1]), "f"(v[2]), "f"(v[3]),
                    "f"(v[4]), "f"(v[5]), "f"(v[6]), "f"(v[7])
                 : "memory");
}

__global__ __launch_bounds__(THREADS, 10)
void mlpcache_gather_kernel(const float* __restrict__ x,
                            const float* __restrict__ cache,
                            const int*   __restrict__ running_seqs,
                            const int*   __restrict__ idx_salient,
                            float*       __restrict__ out)
{
    const int row = blockIdx.x;            // 0 .. 64*512-1 (one row per block)
    const int i   = row >> 9;              // sequence index
    const int r   = row & (ROWS_PER_SEQ - 1);

    // Barrier-free last-wins resolve: each lane checks 2 of the 64 idx
    // entries; REDUX gives winner = max matching j. Loads are L1-broadcast.
    const int lane = threadIdx.x & 31;
    const int v0 = idx_salient[i * K_SALIENT + lane];
    const int v1 = idx_salient[i * K_SALIENT + lane + 32];
    int m = -1;
    if (v0 == r) m = lane;
    if (v1 == r) m = lane + 32;            // lane+32 > lane: overwrite = last-wins
    const int w = __reduce_max_sync(0xFFFFFFFFu, m);

    const float* __restrict__ src = (w >= 0)
        ? x     + ((size_t)(i * K_SALIENT + w)) * HIDDEN
        : cache + ((size_t)running_seqs[i] * ROWS_PER_SEQ + r) * HIDDEN;
    float* __restrict__ dst = out + (size_t)row * HIDDEN;

    // 4 × 256-bit streaming loads front-batched (128 B MLP per thread),
    // then 4 × 256-bit streaming stores. Fully coalesced 4 KB per warp-op set.
    const int c = threadIdx.x * 8;
    float a[8], b[8], d[8], e[8];
    ldg256_cs(src + c,                a);
    ldg256_cs(src + c + THREADS * 8,  b);
    ldg256_cs(src + c + THREADS * 16, d);
    ldg256_cs(src + c + THREADS * 24, e);
    stg256_cs(dst + c,                a);
    stg256_cs(dst + c + THREADS * 8,  b);
    stg256_cs(dst + c + THREADS * 16, d);
    stg256_cs(dst + c + THREADS * 24, e);
}

extern "C" void kernel_launch(void* const* d_in, const int* in_sizes, int n_in,
                              void* d_out, int out_size)
{
    const float* x     = (const float*)d_in[0];
    const float* cache = (const float*)d_in[1];
    const int* running = (const int*)d_in[2];
    const int* idx     = (const int*)d_in[3];
    float* out         = (float*)d_out;

    mlpcache_gather_kernel<<<N_RUNNING * ROWS_PER_SEQ, THREADS>>>(
        x, cache, running, idx, out);
}